// round 1
// baseline (speedup 1.0000x reference)
#include <cuda_runtime.h>

#define D 64
#define MAXN 150000

// Scratch in device globals (no dynamic allocation allowed).
__device__ __align__(16) float g_ego[MAXN * D];        // 38.4 MB, L2-resident
__device__ __align__(16) float g_side[MAXN * D];       // 38.4 MB, L2-resident
__device__ __align__(16) float g_final[MAXN * D * 4];  // 153.6 MB concat buffer

__device__ __forceinline__ float lrelu(float x) { return x >= 0.f ? x : 0.2f * x; }

// ---------------------------------------------------------------------------
// init: ego = concat(user, item); final[:,0:64] = ego; side = 0
// ---------------------------------------------------------------------------
__global__ __launch_bounds__(256) void init_kernel(const float4* __restrict__ user,
                                                   const float4* __restrict__ item,
                                                   int n_users, int n_nodes) {
    int idx = blockIdx.x * 256 + threadIdx.x;
    if (idx >= n_nodes * 16) return;
    int n = idx >> 4, c = idx & 15;
    float4 v = (n < n_users) ? __ldg(user + n * 16 + c)
                             : __ldg(item + (n - n_users) * 16 + c);
    ((float4*)g_ego)[idx] = v;
    ((float4*)g_side)[idx] = make_float4(0.f, 0.f, 0.f, 0.f);
    ((float4*)g_final)[n * 64 + c] = v;
}

// ---------------------------------------------------------------------------
// spmm: side[row] += val * ego[col], 16 threads per edge, one float4 each.
// Vector reduction (red.global.add.v4.f32) — 4x fewer atomic ops.
// ---------------------------------------------------------------------------
__global__ __launch_bounds__(256) void spmm_kernel(const float* __restrict__ vals,
                                                   const int* __restrict__ rows,
                                                   const int* __restrict__ cols,
                                                   int total) {  // total = nnz*16
    int idx = blockIdx.x * 256 + threadIdx.x;
    if (idx >= total) return;
    int e = idx >> 4, c = idx & 15;
    int r = __ldg(rows + e);
    int co = __ldg(cols + e);
    float v = __ldg(vals + e);
    float4 x = __ldg(((const float4*)g_ego) + co * 16 + c);
    float4* dst = ((float4*)g_side) + r * 16 + c;
    asm volatile("red.global.add.v4.f32 [%0], {%1,%2,%3,%4};"
                 :: "l"(dst), "f"(x.x * v), "f"(x.y * v), "f"(x.z * v), "f"(x.w * v)
                 : "memory");
}

// ---------------------------------------------------------------------------
// transform: ego_new = lrelu(side@Wgc+bg) + lrelu((ego*side)@Wbi+bb);
//            final[:, 64*(l+1):] = normalize(ego_new); ego <- ego_new (raw);
//            and zero side for the next layer's accumulation.
// Block = 64 nodes x 64 dims, 256 threads, 4x4 register tile each.
// ---------------------------------------------------------------------------
#define SPAD 68
#define SMEM_BYTES ((2 * 64 * SPAD + 2 * 64 * 64 + 3 * 64) * 4)

__global__ __launch_bounds__(256) void transform_kernel(const float4* __restrict__ Wgc,
                                                        const float* __restrict__ bgc,
                                                        const float4* __restrict__ Wbi,
                                                        const float* __restrict__ bbi,
                                                        int n_nodes, int layer) {
    extern __shared__ float sh[];
    float* Ssh = sh;                     // [64][SPAD] side tile (later: ego_new tile)
    float* Psh = sh + 64 * SPAD;         // [64][SPAD] ego*side tile
    float* Wg  = sh + 2 * 64 * SPAD;     // [64][64]
    float* Wb  = Wg + 64 * 64;           // [64][64]
    float* bg  = Wb + 64 * 64;           // [64]
    float* bb  = bg + 64;                // [64]
    float* nrm = bb + 64;                // [64]

    int tid = threadIdx.x;
    int base = blockIdx.x * 64;

    // load weights + biases
    for (int i = tid; i < 1024; i += 256) {
        ((float4*)Wg)[i] = __ldg(Wgc + i);
        ((float4*)Wb)[i] = __ldg(Wbi + i);
    }
    if (tid < 64) { bg[tid] = __ldg(bgc + tid); bb[tid] = __ldg(bbi + tid); }

    // load side + ego tiles; zero side for next layer's SpMM
    for (int i = tid; i < 1024; i += 256) {
        int r = i >> 4, c = i & 15;
        int node = base + r;
        float4 s = make_float4(0.f, 0.f, 0.f, 0.f);
        float4 e = s;
        if (node < n_nodes) {
            s = ((const float4*)g_side)[node * 16 + c];
            e = ((const float4*)g_ego)[node * 16 + c];
            ((float4*)g_side)[node * 16 + c] = make_float4(0.f, 0.f, 0.f, 0.f);
        }
        *(float4*)&Ssh[r * SPAD + c * 4] = s;
        float4 p = make_float4(s.x * e.x, s.y * e.y, s.z * e.z, s.w * e.w);
        *(float4*)&Psh[r * SPAD + c * 4] = p;
    }
    __syncthreads();

    int r0 = (tid >> 4) * 4;  // node sub-row base
    int c0 = (tid & 15) * 4;  // output-dim base
    float ag[4][4] = {};
    float ab[4][4] = {};

#pragma unroll 8
    for (int k = 0; k < 64; k++) {
        float4 wg = *(const float4*)&Wg[k * 64 + c0];
        float4 wb = *(const float4*)&Wb[k * 64 + c0];
#pragma unroll
        for (int i = 0; i < 4; i++) {
            float s = Ssh[(r0 + i) * SPAD + k];
            float p = Psh[(r0 + i) * SPAD + k];
            ag[i][0] += s * wg.x; ag[i][1] += s * wg.y;
            ag[i][2] += s * wg.z; ag[i][3] += s * wg.w;
            ab[i][0] += p * wb.x; ab[i][1] += p * wb.y;
            ab[i][2] += p * wb.z; ab[i][3] += p * wb.w;
        }
    }
    __syncthreads();  // everyone done reading Ssh before we overwrite it

    float4 bgv = *(const float4*)&bg[c0];
    float4 bbv = *(const float4*)&bb[c0];
#pragma unroll
    for (int i = 0; i < 4; i++) {
        float4 v;
        v.x = lrelu(ag[i][0] + bgv.x) + lrelu(ab[i][0] + bbv.x);
        v.y = lrelu(ag[i][1] + bgv.y) + lrelu(ab[i][1] + bbv.y);
        v.z = lrelu(ag[i][2] + bgv.z) + lrelu(ab[i][2] + bbv.z);
        v.w = lrelu(ag[i][3] + bgv.w) + lrelu(ab[i][3] + bbv.w);
        *(float4*)&Ssh[(r0 + i) * SPAD + c0] = v;
    }
    __syncthreads();

    if (tid < 64) {
        float ss = 0.f;
#pragma unroll
        for (int c = 0; c < 16; c++) {
            float4 v = *(const float4*)&Ssh[tid * SPAD + c * 4];
            ss += v.x * v.x + v.y * v.y + v.z * v.z + v.w * v.w;
        }
        nrm[tid] = 1.0f / fmaxf(sqrtf(ss), 1e-12f);
    }
    __syncthreads();

#pragma unroll
    for (int i = 0; i < 4; i++) {
        int node = base + r0 + i;
        if (node < n_nodes) {
            float4 v = *(const float4*)&Ssh[(r0 + i) * SPAD + c0];
            ((float4*)g_ego)[node * 16 + (c0 >> 2)] = v;  // raw carries forward
            float s = nrm[r0 + i];
            float4 vn = make_float4(v.x * s, v.y * s, v.z * s, v.w * s);
            ((float4*)g_final)[node * 64 + (layer + 1) * 16 + (c0 >> 2)] = vn;
        }
    }
}

// ---------------------------------------------------------------------------
// gather: out = [final[u] | final[nu+i] | final[nu+j]], rows of 256 floats
// ---------------------------------------------------------------------------
__global__ __launch_bounds__(256) void gather_kernel(const int* __restrict__ u,
                                                     const int* __restrict__ ii,
                                                     const int* __restrict__ jj,
                                                     int n_users, int B,
                                                     float4* __restrict__ out) {
    int idx = blockIdx.x * 256 + threadIdx.x;
    int total = 3 * B * 64;
    if (idx >= total) return;
    int c = idx & 63;
    int t = idx >> 6;
    int b = t % B;
    int sel = t / B;
    int row = (sel == 0) ? __ldg(u + b)
            : (sel == 1) ? (n_users + __ldg(ii + b))
                         : (n_users + __ldg(jj + b));
    out[idx] = ((const float4*)g_final)[row * 64 + c];
}

// ---------------------------------------------------------------------------
extern "C" void kernel_launch(void* const* d_in, const int* in_sizes, int n_in,
                              void* d_out, int out_size) {
    const float* user = (const float*)d_in[0];
    const float* item = (const float*)d_in[1];
    const float* Wgc  = (const float*)d_in[2];
    const float* bgc  = (const float*)d_in[3];
    const float* Wbi  = (const float*)d_in[4];
    const float* bbi  = (const float*)d_in[5];
    const float* vals = (const float*)d_in[6];
    const int*   rows = (const int*)d_in[7];
    const int*   cols = (const int*)d_in[8];
    const int*   u    = (const int*)d_in[9];
    const int*   ii   = (const int*)d_in[10];
    const int*   jj   = (const int*)d_in[11];

    int n_users = in_sizes[0] / D;
    int n_items = in_sizes[1] / D;
    int n = n_users + n_items;
    int nnz = in_sizes[6];
    int L = in_sizes[2] / (D * D);
    int B = in_sizes[9];

    cudaFuncSetAttribute(transform_kernel,
                         cudaFuncAttributeMaxDynamicSharedMemorySize, SMEM_BYTES);

    init_kernel<<<(n * 16 + 255) / 256, 256>>>((const float4*)user, (const float4*)item,
                                               n_users, n);
    for (int l = 0; l < L; l++) {
        spmm_kernel<<<(nnz * 16 + 255) / 256, 256>>>(vals, rows, cols, nnz * 16);
        transform_kernel<<<(n + 63) / 64, 256, SMEM_BYTES>>>(
            (const float4*)(Wgc + l * D * D), bgc + l * D,
            (const float4*)(Wbi + l * D * D), bbi + l * D, n, l);
    }
    gather_kernel<<<(3 * B * 64 + 255) / 256, 256>>>(u, ii, jj, n_users, B, (float4*)d_out);
}

// round 2
// speedup vs baseline: 1.8749x; 1.8749x over previous
#include <cuda_runtime.h>

#define D 64
#define MAXN 150016
#define MAXNNZ 2500000
typedef unsigned long long ull;

// Scratch in device globals (no dynamic allocation allowed).
__device__ __align__(16) float g_ego[MAXN * D];        // 38.4 MB, L2-resident
__device__ __align__(16) float g_side[MAXN * D];       // 38.4 MB, L2-resident
__device__ __align__(16) float g_final[MAXN * D * 4];  // 153.6 MB concat buffer
__device__ __align__(16) int2  g_edge[MAXNNZ];         // CSR (col, val) pairs
__device__ int g_hist[MAXN];
__device__ int g_rowptr[MAXN + 1];
__device__ int g_cursor[MAXN];
__device__ int g_partial[1024];

__device__ __forceinline__ float lrelu(float x) { return x >= 0.f ? x : 0.2f * x; }

__device__ __forceinline__ ull ffma2(ull a, ull b, ull c) {
    ull d;
    asm("fma.rn.f32x2 %0, %1, %2, %3;" : "=l"(d) : "l"(a), "l"(b), "l"(c));
    return d;
}

union f2u { float2 f; ull u; };

// ---------------------------------------------------------------------------
// init: ego = concat(user,item); final[:,0:64] = ego; hist = 0
// ---------------------------------------------------------------------------
__global__ __launch_bounds__(256) void init_kernel(const float4* __restrict__ user,
                                                   const float4* __restrict__ item,
                                                   int n_users, int n_nodes) {
    int idx = blockIdx.x * 256 + threadIdx.x;
    if (idx >= n_nodes * 16) return;
    int n = idx >> 4, c = idx & 15;
    float4 v = (n < n_users) ? __ldg(user + n * 16 + c)
                             : __ldg(item + (n - n_users) * 16 + c);
    ((float4*)g_ego)[idx] = v;
    ((float4*)g_final)[n * 64 + c] = v;
    if (c == 0) g_hist[n] = 0;
}

// ---------------------------------------------------------------------------
// CSR build: count -> scan (3 stages) -> scatter
// ---------------------------------------------------------------------------
__global__ __launch_bounds__(256) void count_kernel(const int* __restrict__ rows, int nnz) {
    int e = blockIdx.x * 256 + threadIdx.x;
    if (e < nnz) atomicAdd(&g_hist[__ldg(rows + e)], 1);
}

__global__ __launch_bounds__(256) void scan1_kernel(int n) {
    __shared__ int wsum[8];
    int i = blockIdx.x * 256 + threadIdx.x;
    int lane = threadIdx.x & 31, w = threadIdx.x >> 5;
    int v = (i < n) ? g_hist[i] : 0;
    int x = v;
#pragma unroll
    for (int off = 1; off < 32; off <<= 1) {
        int y = __shfl_up_sync(0xffffffffu, x, off);
        if (lane >= off) x += y;
    }
    if (lane == 31) wsum[w] = x;
    __syncthreads();
    if (threadIdx.x == 0) {
        int run = 0;
#pragma unroll
        for (int q = 0; q < 8; q++) { int t = wsum[q]; wsum[q] = run; run += t; }
        g_partial[blockIdx.x] = run;
    }
    __syncthreads();
    if (i < n) g_rowptr[i] = x - v + wsum[w];
}

__global__ __launch_bounds__(1024) void scan2_kernel(int nblocks) {
    __shared__ int sh[1024];
    int t = threadIdx.x;
    int v = (t < nblocks) ? g_partial[t] : 0;
    sh[t] = v;
    __syncthreads();
#pragma unroll
    for (int off = 1; off < 1024; off <<= 1) {
        int add = (t >= off) ? sh[t - off] : 0;
        __syncthreads();
        sh[t] += add;
        __syncthreads();
    }
    if (t < nblocks) g_partial[t] = sh[t] - v;  // exclusive
}

__global__ __launch_bounds__(256) void finalize_kernel(int n, int nnz) {
    int i = blockIdx.x * 256 + threadIdx.x;
    if (i < n) {
        int off = g_rowptr[i] + g_partial[i >> 8];
        g_rowptr[i] = off;
        g_cursor[i] = off;
    }
    if (i == 0) g_rowptr[n] = nnz;
}

__global__ __launch_bounds__(256) void scatter_kernel(const float* __restrict__ vals,
                                                      const int* __restrict__ rows,
                                                      const int* __restrict__ cols,
                                                      int nnz) {
    int e = blockIdx.x * 256 + threadIdx.x;
    if (e >= nnz) return;
    int r = __ldg(rows + e);
    int pos = atomicAdd(&g_cursor[r], 1);
    g_edge[pos] = make_int2(__ldg(cols + e), __float_as_int(__ldg(vals + e)));
}

// ---------------------------------------------------------------------------
// spmm: one warp per row, 16 lanes x float4 cover D=64, two edges in flight.
// No atomics; every row written exactly once (coalesced).
// ---------------------------------------------------------------------------
__global__ __launch_bounds__(256) void spmm_csr_kernel(int n) {
    int row = (blockIdx.x << 3) + (threadIdx.x >> 5);
    if (row >= n) return;
    int lane = threadIdx.x & 31;
    int half = lane >> 4, c = lane & 15;
    int s = __ldg(&g_rowptr[row]);
    int e = __ldg(&g_rowptr[row + 1]);
    const float4* __restrict__ egos = (const float4*)g_ego;
    float4 acc = make_float4(0.f, 0.f, 0.f, 0.f);
    for (int p = s + half; p < e; p += 2) {
        int2 ed = __ldg(&g_edge[p]);
        float v = __int_as_float(ed.y);
        float4 x = __ldg(egos + ed.x * 16 + c);
        acc.x += v * x.x; acc.y += v * x.y; acc.z += v * x.z; acc.w += v * x.w;
    }
    acc.x += __shfl_xor_sync(0xffffffffu, acc.x, 16);
    acc.y += __shfl_xor_sync(0xffffffffu, acc.y, 16);
    acc.z += __shfl_xor_sync(0xffffffffu, acc.z, 16);
    acc.w += __shfl_xor_sync(0xffffffffu, acc.w, 16);
    if (half == 0) ((float4*)g_side)[row * 16 + c] = acc;
}

// ---------------------------------------------------------------------------
// transform: ego_new = lrelu(side@Wgc+bg) + lrelu((ego*side)@Wbi+bb)
//            g_final slice = normalize(ego_new);  ego <- ego_new (raw)
// 64-node tile, 256 threads, 4x4 per thread, f32x2 packed FMA.
// SD/PD hold pre-duplicated (s,s)/(p,p) pairs so FFMA2 needs no pack MOVs;
// W read as ulonglong2 -> (w0,w1),(w2,w3) packed for free.
// ---------------------------------------------------------------------------
#define RPITCH 66  // float2 units per k-row (even => 16B alignment at even k)
#define TSMEM (2 * 64 * RPITCH * 8 + 2 * 4096 * 4)  // 100352 bytes

__global__ __launch_bounds__(256, 2) void transform_kernel(const float4* __restrict__ Wgc,
                                                           const float* __restrict__ bgc,
                                                           const float4* __restrict__ Wbi,
                                                           const float* __restrict__ bbi,
                                                           int n_nodes, int layer) {
    extern __shared__ char shraw[];
    float2* SD = (float2*)shraw;               // [64 rows][64 k] duplicated (s,s)
    float2* PD = SD + 64 * RPITCH;             // duplicated (p,p)
    float*  Wg = (float*)(PD + 64 * RPITCH);   // [64 k][64 c]
    float*  Wb = Wg + 4096;

    int tid = threadIdx.x;
    int base = blockIdx.x * 64;

    for (int i = tid; i < 1024; i += 256) {
        ((float4*)Wg)[i] = __ldg(Wgc + i);
        ((float4*)Wb)[i] = __ldg(Wbi + i);
        int r = i >> 4, cc = i & 15;
        int node = base + r;
        float4 s4 = make_float4(0.f, 0.f, 0.f, 0.f);
        float4 e4 = s4;
        if (node < n_nodes) {
            s4 = ((const float4*)g_side)[node * 16 + cc];
            e4 = ((const float4*)g_ego)[node * 16 + cc];
        }
        int kb = cc * 4;
        float2* sd = &SD[r * RPITCH + kb];
        float2* pd = &PD[r * RPITCH + kb];
        sd[0] = make_float2(s4.x, s4.x);
        sd[1] = make_float2(s4.y, s4.y);
        sd[2] = make_float2(s4.z, s4.z);
        sd[3] = make_float2(s4.w, s4.w);
        pd[0] = make_float2(s4.x * e4.x, s4.x * e4.x);
        pd[1] = make_float2(s4.y * e4.y, s4.y * e4.y);
        pd[2] = make_float2(s4.z * e4.z, s4.z * e4.z);
        pd[3] = make_float2(s4.w * e4.w, s4.w * e4.w);
    }
    __syncthreads();

    int r0 = (tid >> 4) * 4;   // node sub-rows
    int c0 = (tid & 15) * 4;   // output cols

    ull ag[4][2] = {}, ab[4][2] = {};

#pragma unroll 4
    for (int k = 0; k < 64; k += 2) {
        ulonglong2 wg0 = *(const ulonglong2*)&Wg[k * 64 + c0];
        ulonglong2 wg1 = *(const ulonglong2*)&Wg[(k + 1) * 64 + c0];
        ulonglong2 wb0 = *(const ulonglong2*)&Wb[k * 64 + c0];
        ulonglong2 wb1 = *(const ulonglong2*)&Wb[(k + 1) * 64 + c0];
#pragma unroll
        for (int i = 0; i < 4; i++) {
            ulonglong2 sd = *(const ulonglong2*)&SD[(r0 + i) * RPITCH + k];
            ulonglong2 pd = *(const ulonglong2*)&PD[(r0 + i) * RPITCH + k];
            ag[i][0] = ffma2(sd.x, wg0.x, ag[i][0]);
            ag[i][1] = ffma2(sd.x, wg0.y, ag[i][1]);
            ag[i][0] = ffma2(sd.y, wg1.x, ag[i][0]);
            ag[i][1] = ffma2(sd.y, wg1.y, ag[i][1]);
            ab[i][0] = ffma2(pd.x, wb0.x, ab[i][0]);
            ab[i][1] = ffma2(pd.x, wb0.y, ab[i][1]);
            ab[i][0] = ffma2(pd.y, wb1.x, ab[i][0]);
            ab[i][1] = ffma2(pd.y, wb1.y, ab[i][1]);
        }
    }

    float4 bg4 = __ldg((const float4*)bgc + (c0 >> 2));
    float4 bb4 = __ldg((const float4*)bbi + (c0 >> 2));

    float v[4][4];
    float ssq[4];
#pragma unroll
    for (int i = 0; i < 4; i++) {
        f2u a0, a1, b0, b1;
        a0.u = ag[i][0]; a1.u = ag[i][1];
        b0.u = ab[i][0]; b1.u = ab[i][1];
        v[i][0] = lrelu(a0.f.x + bg4.x) + lrelu(b0.f.x + bb4.x);
        v[i][1] = lrelu(a0.f.y + bg4.y) + lrelu(b0.f.y + bb4.y);
        v[i][2] = lrelu(a1.f.x + bg4.z) + lrelu(b1.f.x + bb4.z);
        v[i][3] = lrelu(a1.f.y + bg4.w) + lrelu(b1.f.y + bb4.w);
        ssq[i] = v[i][0] * v[i][0] + v[i][1] * v[i][1] + v[i][2] * v[i][2] + v[i][3] * v[i][3];
    }
    // reduce ssq across the 16 threads (lanes tid&15) sharing the same rows
#pragma unroll
    for (int off = 1; off < 16; off <<= 1) {
#pragma unroll
        for (int i = 0; i < 4; i++)
            ssq[i] += __shfl_xor_sync(0xffffffffu, ssq[i], off);
    }
#pragma unroll
    for (int i = 0; i < 4; i++) {
        int node = base + r0 + i;
        if (node < n_nodes) {
            float inv = 1.0f / fmaxf(sqrtf(ssq[i]), 1e-12f);
            float4 raw = make_float4(v[i][0], v[i][1], v[i][2], v[i][3]);
            ((float4*)g_ego)[node * 16 + (c0 >> 2)] = raw;
            float4 nn = make_float4(raw.x * inv, raw.y * inv, raw.z * inv, raw.w * inv);
            ((float4*)g_final)[node * 64 + (layer + 1) * 16 + (c0 >> 2)] = nn;
        }
    }
}

// ---------------------------------------------------------------------------
// gather: out = [final[u] | final[nu+i] | final[nu+j]]
// ---------------------------------------------------------------------------
__global__ __launch_bounds__(256) void gather_kernel(const int* __restrict__ u,
                                                     const int* __restrict__ ii,
                                                     const int* __restrict__ jj,
                                                     int n_users, int B,
                                                     float4* __restrict__ out) {
    int idx = blockIdx.x * 256 + threadIdx.x;
    int total = 3 * B * 64;
    if (idx >= total) return;
    int c = idx & 63;
    int t = idx >> 6;
    int b = t % B;
    int sel = t / B;
    int row = (sel == 0) ? __ldg(u + b)
            : (sel == 1) ? (n_users + __ldg(ii + b))
                         : (n_users + __ldg(jj + b));
    out[idx] = ((const float4*)g_final)[row * 64 + c];
}

// ---------------------------------------------------------------------------
extern "C" void kernel_launch(void* const* d_in, const int* in_sizes, int n_in,
                              void* d_out, int out_size) {
    const float* user = (const float*)d_in[0];
    const float* item = (const float*)d_in[1];
    const float* Wgc  = (const float*)d_in[2];
    const float* bgc  = (const float*)d_in[3];
    const float* Wbi  = (const float*)d_in[4];
    const float* bbi  = (const float*)d_in[5];
    const float* vals = (const float*)d_in[6];
    const int*   rows = (const int*)d_in[7];
    const int*   cols = (const int*)d_in[8];
    const int*   u    = (const int*)d_in[9];
    const int*   ii   = (const int*)d_in[10];
    const int*   jj   = (const int*)d_in[11];

    int n_users = in_sizes[0] / D;
    int n_items = in_sizes[1] / D;
    int n = n_users + n_items;
    int nnz = in_sizes[6];
    int L = in_sizes[2] / (D * D);
    int B = in_sizes[9];

    cudaFuncSetAttribute(transform_kernel,
                         cudaFuncAttributeMaxDynamicSharedMemorySize, TSMEM);

    init_kernel<<<(n * 16 + 255) / 256, 256>>>((const float4*)user, (const float4*)item,
                                               n_users, n);
    // CSR build (amortized over L spmm layers)
    int eb = (nnz + 255) / 256;
    int nb = (n + 255) / 256;
    count_kernel<<<eb, 256>>>(rows, nnz);
    scan1_kernel<<<nb, 256>>>(n);
    scan2_kernel<<<1, 1024>>>(nb);
    finalize_kernel<<<nb, 256>>>(n, nnz);
    scatter_kernel<<<eb, 256>>>(vals, rows, cols, nnz);

    for (int l = 0; l < L; l++) {
        spmm_csr_kernel<<<(n + 7) / 8, 256>>>(n);
        transform_kernel<<<(n + 63) / 64, 256, TSMEM>>>(
            (const float4*)(Wgc + l * D * D), bgc + l * D,
            (const float4*)(Wbi + l * D * D), bbi + l * D, n, l);
    }
    gather_kernel<<<(3 * B * 64 + 255) / 256, 256>>>(u, ii, jj, n_users, B, (float4*)d_out);
}